// round 15
// baseline (speedup 1.0000x reference)
#include <cuda_runtime.h>
#include <cuda_bf16.h>
#include <math.h>
#include <stdint.h>

// Problem constants (fixed by the reference)
#define NN 50000
#define NE 600000
#define NG 64
#define DH 128
#define DLAT 64
#define MAXD 128          // degree buckets (max deg ~40 for this graph)
#define NJ 20             // GEMM jobs: 4 h (k32) + 16 agg (k32); K=640
#define MAXB 1024         // fixed GEMM grid
#define STGU 7680         // u32 per smem stage
#define NSTG 3
#define SMEM_BYTES (NSTG * STGU * 4)

// ---------------- device scratch ------------------------------------------
__device__ int   g_deg[NN];
__device__ int   g_off[NN + 1];
__device__ int   g_cur[NN];
__device__ int   g_csr[NE];
__device__ int   g_bsum[64];
__device__ float g_delta[1];
__device__ float g_h0[(size_t)NN * DH];
__device__ float g_h1[(size_t)NN * DH];
__device__ unsigned g_Hh[(size_t)NN * 64];    // slot-permuted h image hi
__device__ unsigned g_Hl[(size_t)NN * 64];
__device__ unsigned g_Agh[(size_t)NN * 256];  // slot-permuted agg image hi
__device__ unsigned g_Agl[(size_t)NN * 256];
__device__ unsigned g_WhImg[3 * 4 * 4096];    // per-layer Wh jobs
__device__ unsigned g_WcImg[(size_t)3 * MAXD * 16 * 4096]; // per (layer,deg) Wc jobs
__device__ int   g_dcnt[MAXD];
__device__ int   g_dstart[MAXD];
__device__ int   g_dcur[MAXD];
__device__ int   g_rank[NN];      // node -> slot
__device__ int   g_s2n[NN];       // slot -> node
__device__ int   g_blk_deg[MAXB];
__device__ int   g_blk_row0[MAXB];
__device__ int   g_blk_end[MAXB];
__device__ int   g_nblk[1];
__device__ float g_pool[NG * DH];

// ---------------- helpers --------------------------------------------------
__device__ __forceinline__ void split_pair(float f0, float f1,
                                           unsigned& hi, unsigned& lo) {
    __nv_bfloat16 h0 = __float2bfloat16_rn(f0);
    __nv_bfloat16 h1 = __float2bfloat16_rn(f1);
    float r0 = f0 - __bfloat162float(h0);
    float r1 = f1 - __bfloat162float(h1);
    __nv_bfloat162 H; H.x = h0; H.y = h1;
    __nv_bfloat162 L = __floats2bfloat162_rn(r0, r1);
    hi = *reinterpret_cast<unsigned*>(&H);
    lo = *reinterpret_cast<unsigned*>(&L);
}
__device__ __forceinline__ void mma_bf16(float* d, const unsigned* a,
                                         const unsigned* b) {
    asm volatile(
        "mma.sync.aligned.m16n8k16.row.col.f32.bf16.bf16.f32 "
        "{%0,%1,%2,%3}, {%4,%5,%6,%7}, {%8,%9}, {%0,%1,%2,%3};\n"
        : "+f"(d[0]), "+f"(d[1]), "+f"(d[2]), "+f"(d[3])
        : "r"(a[0]), "r"(a[1]), "r"(a[2]), "r"(a[3]), "r"(b[0]), "r"(b[1]));
}
__device__ __forceinline__ void ldsm4(unsigned& r0, unsigned& r1,
                                      unsigned& r2, unsigned& r3, uint32_t a) {
    asm volatile("ldmatrix.sync.aligned.m8n8.x4.shared.b16 {%0,%1,%2,%3}, [%4];"
                 : "=r"(r0), "=r"(r1), "=r"(r2), "=r"(r3) : "r"(a));
}
__device__ __forceinline__ uint32_t smem_u32(const void* p) {
    uint32_t a;
    asm("{ .reg .u64 t; cvta.to.shared.u64 t, %1; cvt.u32.u64 %0, t; }"
        : "=r"(a) : "l"(p));
    return a;
}
__device__ __forceinline__ void cp16(uint32_t dst, const void* src) {
    asm volatile("cp.async.cg.shared.global [%0], [%1], 16;"
                 :: "r"(dst), "l"(src));
}
#define CP_COMMIT() asm volatile("cp.async.commit_group;" ::: "memory")
#define CP_WAIT1()  asm volatile("cp.async.wait_group 1;" ::: "memory")

// ---------------- graph prep ----------------------------------------------
__global__ void hist_kernel(const int* __restrict__ ei) {
    int e = blockIdx.x * blockDim.x + threadIdx.x;
    int stride = gridDim.x * blockDim.x;
    for (; e < NE; e += stride) atomicAdd(&g_deg[ei[NE + e]], 1);
}
__global__ void scan1_kernel() {
    __shared__ int sh[1024];
    int b = blockIdx.x, t = threadIdx.x;
    int i = b * 1024 + t;
    int v = (i < NN) ? g_deg[i] : 0;
    sh[t] = v;
    __syncthreads();
    #pragma unroll
    for (int s = 1; s < 1024; s <<= 1) {
        int add = (t >= s) ? sh[t - s] : 0;
        __syncthreads();
        sh[t] += add;
        __syncthreads();
    }
    if (i < NN) g_off[i] = sh[t] - v;
    if (t == 1023) g_bsum[b] = sh[1023];
}
__global__ void scan2_kernel(int nblk) {
    if (threadIdx.x == 0) {
        int c = 0;
        for (int b = 0; b < nblk; b++) { int s = g_bsum[b]; g_bsum[b] = c; c += s; }
        g_off[NN] = c;
    }
}
// scan3 also zeroes g_cur / degree-bucket counters
__global__ void scan3_kernel() {
    int i = blockIdx.x * 1024 + threadIdx.x;
    if (i < NN) {
        g_off[i] += g_bsum[blockIdx.x];
        g_cur[i] = 0;
    }
    if (blockIdx.x == 0 && threadIdx.x < MAXD) {
        g_dcnt[threadIdx.x] = 0;
        g_dcur[threadIdx.x] = 0;
    }
}
__global__ void scatter_kernel(const int* __restrict__ ei) {
    int e = blockIdx.x * blockDim.x + threadIdx.x;
    int stride = gridDim.x * blockDim.x;
    for (; e < NE; e += stride) {
        int dst = ei[NE + e];
        int pos = g_off[dst] + atomicAdd(&g_cur[dst], 1);
        g_csr[pos] = ei[e];
    }
}
// fused: delta accumulation + degree histogram
__global__ void delta_dhist_kernel() {
    int n = blockIdx.x * blockDim.x + threadIdx.x;
    float s = 0.f;
    if (n < NN) {
        int d = g_deg[n];
        s = logf((float)d + 1.f);
        atomicAdd(&g_dcnt[min(d, MAXD - 1)], 1);
    }
    #pragma unroll
    for (int o = 16; o > 0; o >>= 1) s += __shfl_down_sync(0xffffffffu, s, o);
    __shared__ float sh[8];
    int lane = threadIdx.x & 31, wid = threadIdx.x >> 5;
    if (lane == 0) sh[wid] = s;
    __syncthreads();
    if (wid == 0) {
        float v = (lane < 8) ? sh[lane] : 0.f;
        #pragma unroll
        for (int o = 4; o > 0; o >>= 1) v += __shfl_down_sync(0xffffffffu, v, o);
        if (lane == 0) atomicAdd(&g_delta[0], v);
    }
}
// fused: degree-bucket exclusive scan + block map
__global__ void dscan_blkmap_kernel() {
    if (threadIdx.x == 0) {
        int c = 0;
        for (int d = 0; d < MAXD; d++) { g_dstart[d] = c; c += g_dcnt[d]; }
        int nb = 0;
        for (int d = 0; d < MAXD; d++) {
            int cnt = g_dcnt[d], s = g_dstart[d];
            for (int r = 0; r < cnt; r += 64) {
                g_blk_deg[nb] = d;
                g_blk_row0[nb] = s + r;
                g_blk_end[nb] = s + cnt;
                nb++;
            }
        }
        g_nblk[0] = nb;
    }
}
__global__ void rank_kernel() {
    int n = blockIdx.x * blockDim.x + threadIdx.x;
    if (n >= NN) return;
    int d = min(g_deg[n], MAXD - 1);
    int pos = g_dstart[d] + atomicAdd(&g_dcur[d], 1);
    g_rank[n] = pos;
    g_s2n[pos] = n;
}

// ---------------- W images (layer selected by blockIdx.z) -------------------
__global__ void whsplit_kernel(const float* __restrict__ Wa,
                               const float* __restrict__ Wb,
                               const float* __restrict__ Wc,
                               unsigned* __restrict__ img0) {
    int i = blockIdx.x * blockDim.x + threadIdx.x;
    if (i >= 4 * 2048) return;
    const float* W = (blockIdx.z == 0) ? Wa : (blockIdx.z == 1) ? Wb : Wc;
    unsigned* img = img0 + (size_t)blockIdx.z * 4 * 4096;
    int n = i & 127;
    int rest = i >> 7;
    int c = rest & 15;
    int j = rest >> 4;
    int kg = j * 32 + 2 * c;
    unsigned hi, lo;
    split_pair(W[(size_t)kg * DH + n], W[(size_t)(kg + 1) * DH + n], hi, lo);
    img[(size_t)j * 4096 + n * 16 + c] = hi;
    img[(size_t)j * 4096 + 2048 + n * 16 + c] = lo;
}

// Wc(d) = W1 + amp(d) W2 + att(d) W3 (512x128) -> 16 jobs per degree.
__global__ void wcomb_kernel(const float* __restrict__ Wa,
                             const float* __restrict__ Wb,
                             const float* __restrict__ Wcc,
                             unsigned* __restrict__ img0) {
    int d = blockIdx.x;
    if (g_dcnt[d] == 0) return;
    const float* W = (blockIdx.z == 0) ? Wa : (blockIdx.z == 1) ? Wb : Wcc;
    unsigned* img = img0 + (size_t)blockIdx.z * MAXD * 16 * 4096;
    float dlt = g_delta[0] * (1.f / (float)NN);
    float logd = logf((float)d + 1.f);
    float amp = logd / dlt;
    float att = dlt / fmaxf(logd, 1e-5f);
    unsigned* dst = img + (size_t)d * 16 * 4096;
    for (int idx = blockIdx.y * 256 + threadIdx.x; idx < 32768; idx += 32 * 256) {
        int n = idx & 127;
        int rest = idx >> 7;
        int c = rest & 15;
        int j = rest >> 4;
        int kg = j * 32 + 2 * c;
        float v0 = W[(size_t)(128 + kg) * DH + n]
                 + amp * W[(size_t)(640 + kg) * DH + n]
                 + att * W[(size_t)(1152 + kg) * DH + n];
        float v1 = W[(size_t)(129 + kg) * DH + n]
                 + amp * W[(size_t)(641 + kg) * DH + n]
                 + att * W[(size_t)(1153 + kg) * DH + n];
        unsigned hi, lo;
        split_pair(v0, v1, hi, lo);
        dst[(size_t)j * 4096 + n * 16 + c] = hi;
        dst[(size_t)j * 4096 + 2048 + n * 16 + c] = lo;
    }
}

// ---------------- x split (slot-permuted) -----------------------------------
__global__ void xsplit_kernel(const float* __restrict__ x) {
    int i = blockIdx.x * blockDim.x + threadIdx.x;
    if (i >= NN * 64) return;
    int n = i >> 6, p = i & 63;
    int slot = g_rank[n];
    unsigned hi, lo;
    split_pair(x[(size_t)n * DH + 2 * p], x[(size_t)n * DH + 2 * p + 1], hi, lo);
    g_Hh[(size_t)slot * 64 + p] = hi;
    g_Hl[(size_t)slot * 64 + p] = lo;
}

// ---------------- fused agg + bf16x3 GEMM, degree-bucketed -------------------
// Phase 0: each block aggregates its own 64 slots (warp-per-node, MLP=8) and
// writes the split agg image rows it will consume (L2-hot).
// Phase 1: validated 3-stage cp.async + ldmatrix bf16x3 mainloop.
__device__ __forceinline__ void agg_one_node(
        const float* __restrict__ h, int n, int lane, int slot) {
    int beg = g_off[n], end = g_off[n + 1];
    int d = end - beg;
    float s[4] = {0.f, 0.f, 0.f, 0.f};
    float ss[4] = {0.f, 0.f, 0.f, 0.f};
    float mx[4], mn[4];
    #pragma unroll
    for (int i = 0; i < 4; i++) {
        mx[i] = __int_as_float(0xff800000);
        mn[i] = __int_as_float(0x7f800000);
    }
    const float4* hv = (const float4*)h;
    int e = beg;
    for (; e + 8 <= end; e += 8) {
        int idx[8];
        #pragma unroll
        for (int u = 0; u < 8; u++) idx[u] = g_csr[e + u];
        float4 m[8];
        #pragma unroll
        for (int u = 0; u < 8; u++) m[u] = hv[(size_t)idx[u] * 32 + lane];
        #pragma unroll
        for (int u = 0; u < 8; u++) {
            const float* mp = (const float*)&m[u];
            #pragma unroll
            for (int i = 0; i < 4; i++) {
                float v = mp[i];
                s[i] += v; ss[i] += v * v;
                mx[i] = fmaxf(mx[i], v); mn[i] = fminf(mn[i], v);
            }
        }
    }
    for (; e < end; e++) {
        float4 m0 = hv[(size_t)g_csr[e] * 32 + lane];
        const float* mp = (const float*)&m0;
        #pragma unroll
        for (int i = 0; i < 4; i++) {
            float v = mp[i];
            s[i] += v; ss[i] += v * v;
            mx[i] = fmaxf(mx[i], v); mn[i] = fminf(mn[i], v);
        }
    }
    float inv = 1.f / fmaxf((float)d, 1.f);
    float mean[4], stdv[4], mxa[4], mna[4];
    #pragma unroll
    for (int i = 0; i < 4; i++) {
        mean[i] = s[i] * inv;
        float var = fmaxf(ss[i] * inv - mean[i] * mean[i], 0.f);
        stdv[i] = sqrtf(var + 1e-5f);
        mxa[i] = (d == 0) ? 0.f : mx[i];
        mna[i] = (d == 0) ? 0.f : mn[i];
    }
    size_t rowb = (size_t)slot * 256;
    unsigned hi, lo;
    split_pair(mean[0], mean[1], hi, lo);
    g_Agh[rowb + 2 * lane] = hi;     g_Agl[rowb + 2 * lane] = lo;
    split_pair(mean[2], mean[3], hi, lo);
    g_Agh[rowb + 2 * lane + 1] = hi; g_Agl[rowb + 2 * lane + 1] = lo;
    split_pair(mxa[0], mxa[1], hi, lo);
    g_Agh[rowb + 64 + 2 * lane] = hi;     g_Agl[rowb + 64 + 2 * lane] = lo;
    split_pair(mxa[2], mxa[3], hi, lo);
    g_Agh[rowb + 64 + 2 * lane + 1] = hi; g_Agl[rowb + 64 + 2 * lane + 1] = lo;
    split_pair(mna[0], mna[1], hi, lo);
    g_Agh[rowb + 128 + 2 * lane] = hi;     g_Agl[rowb + 128 + 2 * lane] = lo;
    split_pair(mna[2], mna[3], hi, lo);
    g_Agh[rowb + 128 + 2 * lane + 1] = hi; g_Agl[rowb + 128 + 2 * lane + 1] = lo;
    split_pair(stdv[0], stdv[1], hi, lo);
    g_Agh[rowb + 192 + 2 * lane] = hi;     g_Agl[rowb + 192 + 2 * lane] = lo;
    split_pair(stdv[2], stdv[3], hi, lo);
    g_Agh[rowb + 192 + 2 * lane + 1] = hi; g_Agl[rowb + 192 + 2 * lane + 1] = lo;
}

__global__ __launch_bounds__(256, 2) void gemm_deg_kernel(
        const float* __restrict__ hin,
        const unsigned* __restrict__ WhImg, const unsigned* __restrict__ WcImg,
        const float* __restrict__ bias, float* __restrict__ hout,
        int write_split) {
    int b = blockIdx.x;
    if (b >= g_nblk[0]) return;
    extern __shared__ unsigned smem_u[];
    const uint32_t sbase = smem_u32(smem_u);

    const int row0 = g_blk_row0[b];
    const int blkend = g_blk_end[b];
    const unsigned* Wc = WcImg + (size_t)g_blk_deg[b] * 16 * 4096;

    const int tid = threadIdx.x;
    const int lane = tid & 31, wid = tid >> 5;

    // ---- phase 0: aggregate this block's 64 slots (warp per node) ----
    #pragma unroll 1
    for (int i = 0; i < 8; i++) {
        int slot = row0 + wid * 8 + i;
        if (slot < blkend) agg_one_node(hin, g_s2n[slot], lane, slot);
    }
    __syncthreads();   // block-scope fence: agg writes visible to cp.async below

    const int warp_m = wid >> 2;   // 0..1 (32 rows)
    const int warp_n = wid & 3;    // 0..3 (32 cols)
    const int lr = lane >> 2, lc = lane & 3;
    const int lg = lane >> 3, l8 = lane & 7;
    const int a_row = ((lg & 1) << 3) + l8;
    const int a_col = (lg >> 1) << 2;
    const int b_row = ((lg >> 1) << 3) + l8;
    const int b_col = (lg & 1) << 2;
    const int a_base = (warp_m * 32 + a_row) * 20 + a_col;
    const int b_base = 2560 + (warp_n * 32 + b_row) * 20 + b_col;

    float acc[2][4][4];
    #pragma unroll
    for (int mt = 0; mt < 2; mt++)
        #pragma unroll
        for (int nt = 0; nt < 4; nt++)
            #pragma unroll
            for (int e = 0; e < 4; e++) acc[mt][nt][e] = 0.f;

    auto load_stage = [&](int j, int slot) {
        uint32_t base = sbase + slot * (STGU * 4);
        const unsigned *Ah, *Al, *Bsrc;
        int K2, coff;
        if (j < 4) {
            Ah = g_Hh; Al = g_Hl; K2 = 64; coff = j * 16;
            Bsrc = WhImg + (size_t)j * 4096;
        } else {
            Ah = g_Agh; Al = g_Agl; K2 = 256; coff = (j - 4) * 16;
            Bsrc = Wc + (size_t)(j - 4) * 4096;
        }
        #pragma unroll
        for (int c0 = 0; c0 < 6; c0++) {
            int c = c0 * 256 + tid;
            uint32_t dst;
            const unsigned* src;
            if (c < 512) {
                int half = (c >= 256) ? 1 : 0;
                int rem = c - half * 256;
                int r = rem >> 2, q = rem & 3;
                int slotr = min(row0 + r, blkend - 1);
                src = (half ? Al : Ah) + (size_t)slotr * K2 + coff + q * 4;
                dst = base + (half * 1280 + r * 20 + q * 4) * 4;
            } else {
                int cb = c - 512;
                int half = cb >> 9;
                int rem = cb & 511;
                int r = rem >> 2, q = rem & 3;
                src = Bsrc + half * 2048 + r * 16 + q * 4;
                dst = base + (2560 + half * 2560 + r * 20 + q * 4) * 4;
            }
            cp16(dst, src);
        }
        CP_COMMIT();
    };

    load_stage(0, 0);
    load_stage(1, 1);

    for (int j = 0; j < NJ; j++) {
        CP_WAIT1();
        __syncthreads();
        if (j + 2 < NJ) load_stage(j + 2, (j + 2) % NSTG);
        else CP_COMMIT();

        uint32_t st = sbase + (j % NSTG) * (STGU * 4);
        #pragma unroll
        for (int kb = 0; kb < 16; kb += 8) {
            unsigned ah[2][4], al[2][4];
            #pragma unroll
            for (int mt = 0; mt < 2; mt++) {
                uint32_t ad = st + (uint32_t)(a_base + mt * 320 + kb) * 4;
                ldsm4(ah[mt][0], ah[mt][1], ah[mt][2], ah[mt][3], ad);
                ldsm4(al[mt][0], al[mt][1], al[mt][2], al[mt][3], ad + 1280 * 4);
            }
            #pragma unroll
            for (int p = 0; p < 2; p++) {
                unsigned bh[4], bl[4];
                uint32_t bp = st + (uint32_t)(b_base + p * 320 + kb) * 4;
                ldsm4(bh[0], bh[1], bh[2], bh[3], bp);
                ldsm4(bl[0], bl[1], bl[2], bl[3], bp + 2560 * 4);
                #pragma unroll
                for (int q = 0; q < 2; q++) {
                    int nt = 2 * p + q;
                    #pragma unroll
                    for (int mt = 0; mt < 2; mt++) {
                        mma_bf16(acc[mt][nt], ah[mt], &bh[2 * q]);
                        mma_bf16(acc[mt][nt], al[mt], &bh[2 * q]);
                        mma_bf16(acc[mt][nt], ah[mt], &bl[2 * q]);
                    }
                }
            }
        }
    }

    // ---- epilogue: bias + relu, scatter to node order, optional h-image -----
    #pragma unroll
    for (int mt = 0; mt < 2; mt++)
        #pragma unroll
        for (int nt = 0; nt < 4; nt++) {
            int col0 = warp_n * 32 + nt * 8 + 2 * lc;
            float b0 = bias[col0], b1 = bias[col0 + 1];
            #pragma unroll
            for (int rh = 0; rh < 2; rh++) {
                int slot = row0 + warp_m * 32 + mt * 16 + lr + rh * 8;
                if (slot >= blkend) continue;
                int node = g_s2n[slot];
                int e0 = rh * 2;
                float2 v;
                v.x = fmaxf(acc[mt][nt][e0] + b0, 0.f);
                v.y = fmaxf(acc[mt][nt][e0 + 1] + b1, 0.f);
                *(float2*)&hout[(size_t)node * DH + col0] = v;
                if (write_split) {
                    unsigned hi, lo;
                    split_pair(v.x, v.y, hi, lo);
                    g_Hh[(size_t)slot * 64 + (col0 >> 1)] = hi;
                    g_Hl[(size_t)slot * 64 + (col0 >> 1)] = lo;
                }
            }
        }
}

// ---------------- pooling + bn/fc --------------------------------------------
#define POOL_NB 256
__global__ __launch_bounds__(128) void pool_kernel(
        const float* __restrict__ h, const int* __restrict__ batch) {
    int n0 = blockIdx.x * POOL_NB;
    int t = threadIdx.x;
    int nend = min(n0 + POOL_NB, NN);
    int cnt = nend - n0;
    __shared__ int sbm[POOL_NB];
    for (int i = t; i < cnt; i += 128) sbm[i] = batch[n0 + i];
    __syncthreads();
    float acc = 0.f;
    int cur = sbm[0];
    for (int i = 0; i < cnt; i++) {
        int b = sbm[i];
        if (b != cur) {
            atomicAdd(&g_pool[cur * DH + t], acc);
            acc = 0.f; cur = b;
        }
        acc += h[(size_t)(n0 + i) * DH + t];
    }
    atomicAdd(&g_pool[cur * DH + t], acc);
}

__global__ __launch_bounds__(512) void bnfc_kernel(
        const float* __restrict__ gamma, const float* __restrict__ beta,
        const float* __restrict__ fcW, const float* __restrict__ fcb,
        float* __restrict__ out) {
    __shared__ float sp[NG * DH];
    int t = threadIdx.x;
    for (int i = t; i < NG * DH; i += 512) sp[i] = g_pool[i];
    __syncthreads();
    if (t < 128) {
        float m = 0.f;
        #pragma unroll 4
        for (int g = 0; g < NG; g++) m += sp[g * DH + t];
        m *= (1.f / NG);
        float v = 0.f;
        #pragma unroll 4
        for (int g = 0; g < NG; g++) { float d = sp[g * DH + t] - m; v += d * d; }
        v *= (1.f / NG);
        float rs = rsqrtf(v + 1e-5f);
        float ga = gamma[t], be = beta[t];
        for (int g = 0; g < NG; g++)
            sp[g * DH + t] = (sp[g * DH + t] - m) * rs * ga + be;
    }
    __syncthreads();
    for (int i = t; i < NG * DLAT; i += 512) {
        int g = i / DLAT, jj = i % DLAT;
        float s = fcb[jj];
        #pragma unroll 8
        for (int c = 0; c < DH; c++) s += sp[g * DH + c] * fcW[c * DLAT + jj];
        out[i] = s;
    }
}

// ---------------- launch ------------------------------------------------------
extern "C" void kernel_launch(void* const* d_in, const int* in_sizes, int n_in,
                              void* d_out, int out_size) {
    const float* x     = (const float*)d_in[0];
    const int*   ei    = (const int*)d_in[1];
    const int*   batch = (const int*)d_in[2];
    const float* W0 = (const float*)d_in[3];  const float* b0 = (const float*)d_in[4];
    const float* W1 = (const float*)d_in[5];  const float* b1 = (const float*)d_in[6];
    const float* W2 = (const float*)d_in[7];  const float* b2 = (const float*)d_in[8];
    const float* gamma = (const float*)d_in[9];
    const float* beta  = (const float*)d_in[10];
    const float* fcW   = (const float*)d_in[11];
    const float* fcb   = (const float*)d_in[12];
    float* out = (float*)d_out;

    void *p_deg, *p_delta, *p_pool, *p_h0, *p_h1, *p_wh, *p_wc;
    cudaGetSymbolAddress(&p_deg,   g_deg);
    cudaGetSymbolAddress(&p_delta, g_delta);
    cudaGetSymbolAddress(&p_pool,  g_pool);
    cudaGetSymbolAddress(&p_h0,    g_h0);
    cudaGetSymbolAddress(&p_h1,    g_h1);
    cudaGetSymbolAddress(&p_wh,    g_WhImg);
    cudaGetSymbolAddress(&p_wc,    g_WcImg);
    float* h0 = (float*)p_h0;
    float* h1 = (float*)p_h1;
    unsigned* whimg = (unsigned*)p_wh;
    unsigned* wcimg = (unsigned*)p_wc;

    cudaFuncSetAttribute(gemm_deg_kernel,
                         cudaFuncAttributeMaxDynamicSharedMemorySize, SMEM_BYTES);

    cudaMemsetAsync(p_deg,   0, NN * sizeof(int));
    cudaMemsetAsync(p_delta, 0, sizeof(float));
    cudaMemsetAsync(p_pool,  0, NG * DH * sizeof(float));

    int eblocks = (NE + 1023) / 1024;
    int sblocks = (NN + 1023) / 1024;
    hist_kernel<<<eblocks, 1024>>>(ei);
    scan1_kernel<<<sblocks, 1024>>>();
    scan2_kernel<<<1, 32>>>(sblocks);
    scan3_kernel<<<sblocks, 1024>>>();
    scatter_kernel<<<eblocks, 1024>>>(ei);
    delta_dhist_kernel<<<(NN + 255) / 256, 256>>>();
    dscan_blkmap_kernel<<<1, 32>>>();
    rank_kernel<<<(NN + 255) / 256, 256>>>();

    // W images (single launch each, layer = blockIdx.z)
    const size_t WHL = 4 * 4096;
    const size_t WCL = (size_t)MAXD * 16 * 4096;
    whsplit_kernel<<<dim3((4 * 2048 + 255) / 256, 1, 3), 256>>>(W0, W1, W2, whimg);
    wcomb_kernel<<<dim3(MAXD, 32, 3), 256>>>(W0, W1, W2, wcimg);

    xsplit_kernel<<<(NN * 64 + 255) / 256, 256>>>(x);

    // fused agg+gemm per layer
    gemm_deg_kernel<<<MAXB, 256, SMEM_BYTES>>>(x,  whimg,           wcimg,           b0, h0, 1);
    gemm_deg_kernel<<<MAXB, 256, SMEM_BYTES>>>(h0, whimg + WHL,     wcimg + WCL,     b1, h1, 1);
    gemm_deg_kernel<<<MAXB, 256, SMEM_BYTES>>>(h1, whimg + 2 * WHL, wcimg + 2 * WCL, b2, h0, 0);

    pool_kernel<<<(NN + POOL_NB - 1) / POOL_NB, 128>>>(h0, batch);
    bnfc_kernel<<<1, 512>>>(gamma, beta, fcW, fcb, out);
}

// round 16
// speedup vs baseline: 1.2237x; 1.2237x over previous
#include <cuda_runtime.h>
#include <cuda_bf16.h>
#include <math.h>
#include <stdint.h>

// Problem constants (fixed by the reference)
#define NN 50000
#define NE 600000
#define NG 64
#define DH 128
#define DLAT 64
#define MAXD 128          // degree buckets (max deg ~40 for this graph)
#define NJ 20             // GEMM jobs: 4 h (k32) + 16 agg (k32); K=640
#define MAXB 1024         // fixed GEMM grid
#define STGU 10240        // u32 per smem stage: A 2*128*20 + B 2*128*20
#define SMEM_BYTES (2 * STGU * 4)

// ---------------- device scratch ------------------------------------------
__device__ int   g_deg[NN];
__device__ int   g_off[NN + 1];
__device__ int   g_cur[NN];
__device__ int   g_csr[NE];
__device__ int   g_bsum[64];
__device__ float g_delta[1];
__device__ float g_h0[(size_t)NN * DH];
__device__ float g_h1[(size_t)NN * DH];
__device__ unsigned g_Hh[(size_t)NN * 64];    // slot-permuted h image hi
__device__ unsigned g_Hl[(size_t)NN * 64];
__device__ unsigned g_Agh[(size_t)NN * 256];  // slot-permuted agg image hi
__device__ unsigned g_Agl[(size_t)NN * 256];
__device__ unsigned g_WhImg[3 * 4 * 4096];    // per-layer Wh jobs
__device__ unsigned g_WcImg[(size_t)3 * MAXD * 16 * 4096]; // per (layer,deg) Wc jobs
__device__ int   g_dcnt[MAXD];
__device__ int   g_dstart[MAXD];
__device__ int   g_dcur[MAXD];
__device__ int   g_rank[NN];      // node -> slot
__device__ int   g_s2n[NN];       // slot -> node
__device__ int   g_blk_deg[MAXB];
__device__ int   g_blk_row0[MAXB];
__device__ int   g_blk_end[MAXB];
__device__ int   g_nblk[1];
__device__ float g_pool[NG * DH];

// ---------------- helpers --------------------------------------------------
__device__ __forceinline__ void split_pair(float f0, float f1,
                                           unsigned& hi, unsigned& lo) {
    __nv_bfloat16 h0 = __float2bfloat16_rn(f0);
    __nv_bfloat16 h1 = __float2bfloat16_rn(f1);
    float r0 = f0 - __bfloat162float(h0);
    float r1 = f1 - __bfloat162float(h1);
    __nv_bfloat162 H; H.x = h0; H.y = h1;
    __nv_bfloat162 L = __floats2bfloat162_rn(r0, r1);
    hi = *reinterpret_cast<unsigned*>(&H);
    lo = *reinterpret_cast<unsigned*>(&L);
}
__device__ __forceinline__ void mma_bf16(float* d, const unsigned* a,
                                         const unsigned* b) {
    asm volatile(
        "mma.sync.aligned.m16n8k16.row.col.f32.bf16.bf16.f32 "
        "{%0,%1,%2,%3}, {%4,%5,%6,%7}, {%8,%9}, {%0,%1,%2,%3};\n"
        : "+f"(d[0]), "+f"(d[1]), "+f"(d[2]), "+f"(d[3])
        : "r"(a[0]), "r"(a[1]), "r"(a[2]), "r"(a[3]), "r"(b[0]), "r"(b[1]));
}
__device__ __forceinline__ void ldsm4(unsigned& r0, unsigned& r1,
                                      unsigned& r2, unsigned& r3, uint32_t a) {
    asm volatile("ldmatrix.sync.aligned.m8n8.x4.shared.b16 {%0,%1,%2,%3}, [%4];"
                 : "=r"(r0), "=r"(r1), "=r"(r2), "=r"(r3) : "r"(a));
}
__device__ __forceinline__ uint32_t smem_u32(const void* p) {
    uint32_t a;
    asm("{ .reg .u64 t; cvta.to.shared.u64 t, %1; cvt.u32.u64 %0, t; }"
        : "=r"(a) : "l"(p));
    return a;
}
__device__ __forceinline__ void cp16(uint32_t dst, const void* src) {
    asm volatile("cp.async.cg.shared.global [%0], [%1], 16;"
                 :: "r"(dst), "l"(src));
}
#define CP_COMMIT() asm volatile("cp.async.commit_group;" ::: "memory")
#define CP_WAIT0()  asm volatile("cp.async.wait_group 0;" ::: "memory")

// ---------------- graph prep ----------------------------------------------
__global__ void hist_kernel(const int* __restrict__ ei) {
    int e = blockIdx.x * blockDim.x + threadIdx.x;
    int stride = gridDim.x * blockDim.x;
    for (; e < NE; e += stride) atomicAdd(&g_deg[ei[NE + e]], 1);
}
__global__ void scan1_kernel() {
    __shared__ int sh[1024];
    int b = blockIdx.x, t = threadIdx.x;
    int i = b * 1024 + t;
    int v = (i < NN) ? g_deg[i] : 0;
    sh[t] = v;
    __syncthreads();
    #pragma unroll
    for (int s = 1; s < 1024; s <<= 1) {
        int add = (t >= s) ? sh[t - s] : 0;
        __syncthreads();
        sh[t] += add;
        __syncthreads();
    }
    if (i < NN) g_off[i] = sh[t] - v;
    if (t == 1023) g_bsum[b] = sh[1023];
}
__global__ void scan2_kernel(int nblk) {
    if (threadIdx.x == 0) {
        int c = 0;
        for (int b = 0; b < nblk; b++) { int s = g_bsum[b]; g_bsum[b] = c; c += s; }
        g_off[NN] = c;
    }
}
// scan3 also zeroes g_cur / degree-bucket counters
__global__ void scan3_kernel() {
    int i = blockIdx.x * 1024 + threadIdx.x;
    if (i < NN) {
        g_off[i] += g_bsum[blockIdx.x];
        g_cur[i] = 0;
    }
    if (blockIdx.x == 0 && threadIdx.x < MAXD) {
        g_dcnt[threadIdx.x] = 0;
        g_dcur[threadIdx.x] = 0;
    }
}
__global__ void scatter_kernel(const int* __restrict__ ei) {
    int e = blockIdx.x * blockDim.x + threadIdx.x;
    int stride = gridDim.x * blockDim.x;
    for (; e < NE; e += stride) {
        int dst = ei[NE + e];
        int pos = g_off[dst] + atomicAdd(&g_cur[dst], 1);
        g_csr[pos] = ei[e];
    }
}
// fused: delta accumulation + degree histogram
__global__ void delta_dhist_kernel() {
    int n = blockIdx.x * blockDim.x + threadIdx.x;
    float s = 0.f;
    if (n < NN) {
        int d = g_deg[n];
        s = logf((float)d + 1.f);
        atomicAdd(&g_dcnt[min(d, MAXD - 1)], 1);
    }
    #pragma unroll
    for (int o = 16; o > 0; o >>= 1) s += __shfl_down_sync(0xffffffffu, s, o);
    __shared__ float sh[8];
    int lane = threadIdx.x & 31, wid = threadIdx.x >> 5;
    if (lane == 0) sh[wid] = s;
    __syncthreads();
    if (wid == 0) {
        float v = (lane < 8) ? sh[lane] : 0.f;
        #pragma unroll
        for (int o = 4; o > 0; o >>= 1) v += __shfl_down_sync(0xffffffffu, v, o);
        if (lane == 0) atomicAdd(&g_delta[0], v);
    }
}
// fused: degree-bucket exclusive scan + block map (128-row blocks)
__global__ void dscan_blkmap_kernel() {
    if (threadIdx.x == 0) {
        int c = 0;
        for (int d = 0; d < MAXD; d++) { g_dstart[d] = c; c += g_dcnt[d]; }
        int nb = 0;
        for (int d = 0; d < MAXD; d++) {
            int cnt = g_dcnt[d], s = g_dstart[d];
            for (int r = 0; r < cnt; r += 128) {
                g_blk_deg[nb] = d;
                g_blk_row0[nb] = s + r;
                g_blk_end[nb] = s + cnt;
                nb++;
            }
        }
        g_nblk[0] = nb;
    }
}
__global__ void rank_kernel() {
    int n = blockIdx.x * blockDim.x + threadIdx.x;
    if (n >= NN) return;
    int d = min(g_deg[n], MAXD - 1);
    int pos = g_dstart[d] + atomicAdd(&g_dcur[d], 1);
    g_rank[n] = pos;
    g_s2n[pos] = n;
}

// ---------------- W images (layer selected by blockIdx.z) -------------------
__global__ void whsplit_kernel(const float* __restrict__ Wa,
                               const float* __restrict__ Wb,
                               const float* __restrict__ Wc,
                               unsigned* __restrict__ img0) {
    int i = blockIdx.x * blockDim.x + threadIdx.x;
    if (i >= 4 * 2048) return;
    const float* W = (blockIdx.z == 0) ? Wa : (blockIdx.z == 1) ? Wb : Wc;
    unsigned* img = img0 + (size_t)blockIdx.z * 4 * 4096;
    int n = i & 127;
    int rest = i >> 7;
    int c = rest & 15;
    int j = rest >> 4;
    int kg = j * 32 + 2 * c;
    unsigned hi, lo;
    split_pair(W[(size_t)kg * DH + n], W[(size_t)(kg + 1) * DH + n], hi, lo);
    img[(size_t)j * 4096 + n * 16 + c] = hi;
    img[(size_t)j * 4096 + 2048 + n * 16 + c] = lo;
}

// Wc(d) = W1 + amp(d) W2 + att(d) W3 (512x128) -> 16 jobs per degree.
__global__ void wcomb_kernel(const float* __restrict__ Wa,
                             const float* __restrict__ Wb,
                             const float* __restrict__ Wcc,
                             unsigned* __restrict__ img0) {
    int d = blockIdx.x;
    if (g_dcnt[d] == 0) return;
    const float* W = (blockIdx.z == 0) ? Wa : (blockIdx.z == 1) ? Wb : Wcc;
    unsigned* img = img0 + (size_t)blockIdx.z * MAXD * 16 * 4096;
    float dlt = g_delta[0] * (1.f / (float)NN);
    float logd = logf((float)d + 1.f);
    float amp = logd / dlt;
    float att = dlt / fmaxf(logd, 1e-5f);
    unsigned* dst = img + (size_t)d * 16 * 4096;
    for (int idx = blockIdx.y * 256 + threadIdx.x; idx < 32768; idx += 32 * 256) {
        int n = idx & 127;
        int rest = idx >> 7;
        int c = rest & 15;
        int j = rest >> 4;
        int kg = j * 32 + 2 * c;
        float v0 = W[(size_t)(128 + kg) * DH + n]
                 + amp * W[(size_t)(640 + kg) * DH + n]
                 + att * W[(size_t)(1152 + kg) * DH + n];
        float v1 = W[(size_t)(129 + kg) * DH + n]
                 + amp * W[(size_t)(641 + kg) * DH + n]
                 + att * W[(size_t)(1153 + kg) * DH + n];
        unsigned hi, lo;
        split_pair(v0, v1, hi, lo);
        dst[(size_t)j * 4096 + n * 16 + c] = hi;
        dst[(size_t)j * 4096 + 2048 + n * 16 + c] = lo;
    }
}

// ---------------- x split (slot-permuted) -----------------------------------
__global__ void xsplit_kernel(const float* __restrict__ x) {
    int i = blockIdx.x * blockDim.x + threadIdx.x;
    if (i >= NN * 64) return;
    int n = i >> 6, p = i & 63;
    int slot = g_rank[n];
    unsigned hi, lo;
    split_pair(x[(size_t)n * DH + 2 * p], x[(size_t)n * DH + 2 * p + 1], hi, lo);
    g_Hh[(size_t)slot * 64 + p] = hi;
    g_Hl[(size_t)slot * 64 + p] = lo;
}

// ---------------- aggregation (warp per node, MLP=8) ------------------------
__global__ __launch_bounds__(256) void agg_kernel(const float* __restrict__ h) {
    int wid = threadIdx.x >> 5;
    int lane = threadIdx.x & 31;
    int n = blockIdx.x * 8 + wid;
    if (n >= NN) return;
    int beg = g_off[n], end = g_off[n + 1];
    int d = end - beg;

    float s[4] = {0.f, 0.f, 0.f, 0.f};
    float ss[4] = {0.f, 0.f, 0.f, 0.f};
    float mx[4], mn[4];
    #pragma unroll
    for (int i = 0; i < 4; i++) {
        mx[i] = __int_as_float(0xff800000);
        mn[i] = __int_as_float(0x7f800000);
    }

    const float4* hv = (const float4*)h;
    int col = lane;

    int e = beg;
    for (; e + 8 <= end; e += 8) {
        int idx[8];
        #pragma unroll
        for (int u = 0; u < 8; u++) idx[u] = g_csr[e + u];
        float4 m[8];
        #pragma unroll
        for (int u = 0; u < 8; u++) m[u] = hv[(size_t)idx[u] * 32 + col];
        #pragma unroll
        for (int u = 0; u < 8; u++) {
            const float* mp = (const float*)&m[u];
            #pragma unroll
            for (int i = 0; i < 4; i++) {
                float v = mp[i];
                s[i] += v; ss[i] += v * v;
                mx[i] = fmaxf(mx[i], v); mn[i] = fminf(mn[i], v);
            }
        }
    }
    for (; e < end; e++) {
        float4 m0 = hv[(size_t)g_csr[e] * 32 + col];
        const float* mp = (const float*)&m0;
        #pragma unroll
        for (int i = 0; i < 4; i++) {
            float v = mp[i];
            s[i] += v; ss[i] += v * v;
            mx[i] = fmaxf(mx[i], v); mn[i] = fminf(mn[i], v);
        }
    }

    float inv = 1.f / fmaxf((float)d, 1.f);
    float mean[4], stdv[4], mxa[4], mna[4];
    #pragma unroll
    for (int i = 0; i < 4; i++) {
        mean[i] = s[i] * inv;
        float var = fmaxf(ss[i] * inv - mean[i] * mean[i], 0.f);
        stdv[i] = sqrtf(var + 1e-5f);
        mxa[i] = (d == 0) ? 0.f : mx[i];
        mna[i] = (d == 0) ? 0.f : mn[i];
    }

    size_t rowb = (size_t)g_rank[n] * 256;
    unsigned hi, lo;
    split_pair(mean[0], mean[1], hi, lo);
    g_Agh[rowb + 2 * lane] = hi;     g_Agl[rowb + 2 * lane] = lo;
    split_pair(mean[2], mean[3], hi, lo);
    g_Agh[rowb + 2 * lane + 1] = hi; g_Agl[rowb + 2 * lane + 1] = lo;
    split_pair(mxa[0], mxa[1], hi, lo);
    g_Agh[rowb + 64 + 2 * lane] = hi;     g_Agl[rowb + 64 + 2 * lane] = lo;
    split_pair(mxa[2], mxa[3], hi, lo);
    g_Agh[rowb + 64 + 2 * lane + 1] = hi; g_Agl[rowb + 64 + 2 * lane + 1] = lo;
    split_pair(mna[0], mna[1], hi, lo);
    g_Agh[rowb + 128 + 2 * lane] = hi;     g_Agl[rowb + 128 + 2 * lane] = lo;
    split_pair(mna[2], mna[3], hi, lo);
    g_Agh[rowb + 128 + 2 * lane + 1] = hi; g_Agl[rowb + 128 + 2 * lane + 1] = lo;
    split_pair(stdv[0], stdv[1], hi, lo);
    g_Agh[rowb + 192 + 2 * lane] = hi;     g_Agl[rowb + 192 + 2 * lane] = lo;
    split_pair(stdv[2], stdv[3], hi, lo);
    g_Agh[rowb + 192 + 2 * lane + 1] = hi; g_Agl[rowb + 192 + 2 * lane + 1] = lo;
}

// ---------------- bf16x3 GEMM, degree-bucketed, 128-row blocks ---------------
// 256 threads, 8 warps as 4m x 2n; warp tile 32 rows x 64 cols.
// stage (u32): A hi[128][20]@0 lo@2560; B hi[128][20]@5120 lo@7680.
__global__ __launch_bounds__(256, 2) void gemm_deg_kernel(
        const unsigned* __restrict__ WhImg, const unsigned* __restrict__ WcImg,
        const float* __restrict__ bias, float* __restrict__ hout,
        int write_split) {
    int b = blockIdx.x;
    if (b >= g_nblk[0]) return;
    extern __shared__ unsigned smem_u[];
    const uint32_t sbase = smem_u32(smem_u);

    const int row0 = g_blk_row0[b];
    const int blkend = g_blk_end[b];
    const unsigned* Wc = WcImg + (size_t)g_blk_deg[b] * 16 * 4096;

    const int tid = threadIdx.x;
    const int lane = tid & 31, wid = tid >> 5;
    const int warp_m = wid >> 1;   // 0..3 (32 rows)
    const int warp_n = wid & 1;    // 0..1 (64 cols)
    const int lr = lane >> 2, lc = lane & 3;
    const int lg = lane >> 3, l8 = lane & 7;
    const int a_row = ((lg & 1) << 3) + l8;
    const int a_col = (lg >> 1) << 2;
    const int b_row = ((lg >> 1) << 3) + l8;
    const int b_col = (lg & 1) << 2;
    const int a_base = (warp_m * 32 + a_row) * 20 + a_col;            // + mt*320 + kb
    const int b_base = 5120 + (warp_n * 64 + b_row) * 20 + b_col;     // + p*320 + kb

    float acc[2][8][4];
    #pragma unroll
    for (int mt = 0; mt < 2; mt++)
        #pragma unroll
        for (int nt = 0; nt < 8; nt++)
            #pragma unroll
            for (int e = 0; e < 4; e++) acc[mt][nt][e] = 0.f;

    auto load_stage = [&](int j, int slot) {
        uint32_t base = sbase + slot * (STGU * 4);
        const unsigned *Ah, *Al, *Bsrc;
        int K2, coff;
        if (j < 4) {
            Ah = g_Hh; Al = g_Hl; K2 = 64; coff = j * 16;
            Bsrc = WhImg + (size_t)j * 4096;
        } else {
            Ah = g_Agh; Al = g_Agl; K2 = 256; coff = (j - 4) * 16;
            Bsrc = Wc + (size_t)(j - 4) * 4096;
        }
        #pragma unroll
        for (int c0 = 0; c0 < 8; c0++) {
            int c = c0 * 256 + tid;
            uint32_t dst;
            const unsigned* src;
            if (c < 1024) {
                int half = (c >= 512) ? 1 : 0;
                int rem = c - half * 512;
                int r = rem >> 2, q = rem & 3;
                int slotr = min(row0 + r, blkend - 1);
                src = (half ? Al : Ah) + (size_t)slotr * K2 + coff + q * 4;
                dst = base + (half * 2560 + r * 20 + q * 4) * 4;
            } else {
                int cb = c - 1024;
                int half = cb >> 9;
                int rem = cb & 511;
                int r = rem >> 2, q = rem & 3;
                src = Bsrc + half * 2048 + r * 16 + q * 4;
                dst = base + (5120 + half * 2560 + r * 20 + q * 4) * 4;
            }
            cp16(dst, src);
        }
        CP_COMMIT();
    };

    load_stage(0, 0);

    for (int j = 0; j < NJ; j++) {
        CP_WAIT0();
        __syncthreads();
        if (j + 1 < NJ) load_stage(j + 1, (j + 1) & 1);

        uint32_t st = sbase + (j & 1) * (STGU * 4);
        #pragma unroll
        for (int kb = 0; kb < 16; kb += 8) {
            unsigned ah[2][4], al[2][4];
            #pragma unroll
            for (int mt = 0; mt < 2; mt++) {
                uint32_t ad = st + (uint32_t)(a_base + mt * 320 + kb) * 4;
                ldsm4(ah[mt][0], ah[mt][1], ah[mt][2], ah[mt][3], ad);
                ldsm4(al[mt][0], al[mt][1], al[mt][2], al[mt][3], ad + 2560 * 4);
            }
            #pragma unroll
            for (int p = 0; p < 4; p++) {
                unsigned bh[4], bl[4];
                uint32_t bp = st + (uint32_t)(b_base + p * 320 + kb) * 4;
                ldsm4(bh[0], bh[1], bh[2], bh[3], bp);
                ldsm4(bl[0], bl[1], bl[2], bl[3], bp + 2560 * 4);
                #pragma unroll
                for (int q = 0; q < 2; q++) {
                    int nt = 2 * p + q;
                    #pragma unroll
                    for (int mt = 0; mt < 2; mt++) {
                        mma_bf16(acc[mt][nt], ah[mt], &bh[2 * q]);
                        mma_bf16(acc[mt][nt], al[mt], &bh[2 * q]);
                        mma_bf16(acc[mt][nt], ah[mt], &bl[2 * q]);
                    }
                }
            }
        }
    }

    // ---- epilogue: bias + relu, scatter to node order, optional h-image -----
    #pragma unroll
    for (int mt = 0; mt < 2; mt++)
        #pragma unroll
        for (int nt = 0; nt < 8; nt++) {
            int col0 = warp_n * 64 + nt * 8 + 2 * lc;
            float b0 = bias[col0], b1 = bias[col0 + 1];
            #pragma unroll
            for (int rh = 0; rh < 2; rh++) {
                int slot = row0 + warp_m * 32 + mt * 16 + lr + rh * 8;
                if (slot >= blkend) continue;
                int node = g_s2n[slot];
                int e0 = rh * 2;
                float2 v;
                v.x = fmaxf(acc[mt][nt][e0] + b0, 0.f);
                v.y = fmaxf(acc[mt][nt][e0 + 1] + b1, 0.f);
                *(float2*)&hout[(size_t)node * DH + col0] = v;
                if (write_split) {
                    unsigned hi, lo;
                    split_pair(v.x, v.y, hi, lo);
                    g_Hh[(size_t)slot * 64 + (col0 >> 1)] = hi;
                    g_Hl[(size_t)slot * 64 + (col0 >> 1)] = lo;
                }
            }
        }
}

// ---------------- pooling + bn/fc --------------------------------------------
#define POOL_NB 256
__global__ __launch_bounds__(128) void pool_kernel(
        const float* __restrict__ h, const int* __restrict__ batch) {
    int n0 = blockIdx.x * POOL_NB;
    int t = threadIdx.x;
    int nend = min(n0 + POOL_NB, NN);
    int cnt = nend - n0;
    __shared__ int sbm[POOL_NB];
    for (int i = t; i < cnt; i += 128) sbm[i] = batch[n0 + i];
    __syncthreads();
    float acc = 0.f;
    int cur = sbm[0];
    for (int i = 0; i < cnt; i++) {
        int b = sbm[i];
        if (b != cur) {
            atomicAdd(&g_pool[cur * DH + t], acc);
            acc = 0.f; cur = b;
        }
        acc += h[(size_t)(n0 + i) * DH + t];
    }
    atomicAdd(&g_pool[cur * DH + t], acc);
}

__global__ __launch_bounds__(512) void bnfc_kernel(
        const float* __restrict__ gamma, const float* __restrict__ beta,
        const float* __restrict__ fcW, const float* __restrict__ fcb,
        float* __restrict__ out) {
    __shared__ float sp[NG * DH];
    int t = threadIdx.x;
    for (int i = t; i < NG * DH; i += 512) sp[i] = g_pool[i];
    __syncthreads();
    if (t < 128) {
        float m = 0.f;
        #pragma unroll 4
        for (int g = 0; g < NG; g++) m += sp[g * DH + t];
        m *= (1.f / NG);
        float v = 0.f;
        #pragma unroll 4
        for (int g = 0; g < NG; g++) { float d = sp[g * DH + t] - m; v += d * d; }
        v *= (1.f / NG);
        float rs = rsqrtf(v + 1e-5f);
        float ga = gamma[t], be = beta[t];
        for (int g = 0; g < NG; g++)
            sp[g * DH + t] = (sp[g * DH + t] - m) * rs * ga + be;
    }
    __syncthreads();
    for (int i = t; i < NG * DLAT; i += 512) {
        int g = i / DLAT, jj = i % DLAT;
        float s = fcb[jj];
        #pragma unroll 8
        for (int c = 0; c < DH; c++) s += sp[g * DH + c] * fcW[c * DLAT + jj];
        out[i] = s;
    }
}

// ---------------- launch ------------------------------------------------------
extern "C" void kernel_launch(void* const* d_in, const int* in_sizes, int n_in,
                              void* d_out, int out_size) {
    const float* x     = (const float*)d_in[0];
    const int*   ei    = (const int*)d_in[1];
    const int*   batch = (const int*)d_in[2];
    const float* W0 = (const float*)d_in[3];  const float* b0 = (const float*)d_in[4];
    const float* W1 = (const float*)d_in[5];  const float* b1 = (const float*)d_in[6];
    const float* W2 = (const float*)d_in[7];  const float* b2 = (const float*)d_in[8];
    const float* gamma = (const float*)d_in[9];
    const float* beta  = (const float*)d_in[10];
    const float* fcW   = (const float*)d_in[11];
    const float* fcb   = (const float*)d_in[12];
    float* out = (float*)d_out;

    void *p_deg, *p_delta, *p_pool, *p_h0, *p_h1, *p_wh, *p_wc;
    cudaGetSymbolAddress(&p_deg,   g_deg);
    cudaGetSymbolAddress(&p_delta, g_delta);
    cudaGetSymbolAddress(&p_pool,  g_pool);
    cudaGetSymbolAddress(&p_h0,    g_h0);
    cudaGetSymbolAddress(&p_h1,    g_h1);
    cudaGetSymbolAddress(&p_wh,    g_WhImg);
    cudaGetSymbolAddress(&p_wc,    g_WcImg);
    float* h0 = (float*)p_h0;
    float* h1 = (float*)p_h1;
    unsigned* whimg = (unsigned*)p_wh;
    unsigned* wcimg = (unsigned*)p_wc;

    cudaFuncSetAttribute(gemm_deg_kernel,
                         cudaFuncAttributeMaxDynamicSharedMemorySize, SMEM_BYTES);

    cudaMemsetAsync(p_deg,   0, NN * sizeof(int));
    cudaMemsetAsync(p_delta, 0, sizeof(float));
    cudaMemsetAsync(p_pool,  0, NG * DH * sizeof(float));

    int eblocks = (NE + 1023) / 1024;
    int sblocks = (NN + 1023) / 1024;
    hist_kernel<<<eblocks, 1024>>>(ei);
    scan1_kernel<<<sblocks, 1024>>>();
    scan2_kernel<<<1, 32>>>(sblocks);
    scan3_kernel<<<sblocks, 1024>>>();
    scatter_kernel<<<eblocks, 1024>>>(ei);
    delta_dhist_kernel<<<(NN + 255) / 256, 256>>>();
    dscan_blkmap_kernel<<<1, 32>>>();
    rank_kernel<<<(NN + 255) / 256, 256>>>();

    // W images (single launch each, layer = blockIdx.z)
    const size_t WHL = 4 * 4096;
    const size_t WCL = (size_t)MAXD * 16 * 4096;
    whsplit_kernel<<<dim3((4 * 2048 + 255) / 256, 1, 3), 256>>>(W0, W1, W2, whimg);
    wcomb_kernel<<<dim3(MAXD, 32, 3), 256>>>(W0, W1, W2, wcimg);

    xsplit_kernel<<<(NN * 64 + 255) / 256, 256>>>(x);

    int ablocks = (NN + 7) / 8;   // 6250

    // layer 0
    agg_kernel<<<ablocks, 256>>>(x);
    gemm_deg_kernel<<<MAXB, 256, SMEM_BYTES>>>(whimg, wcimg, b0, h0, 1);
    // layer 1
    agg_kernel<<<ablocks, 256>>>(h0);
    gemm_deg_kernel<<<MAXB, 256, SMEM_BYTES>>>(whimg + WHL, wcimg + WCL, b1, h1, 1);
    // layer 2
    agg_kernel<<<ablocks, 256>>>(h1);
    gemm_deg_kernel<<<MAXB, 256, SMEM_BYTES>>>(whimg + 2 * WHL, wcimg + 2 * WCL,
                                               b2, h0, 0);

    pool_kernel<<<(NN + POOL_NB - 1) / POOL_NB, 128>>>(h0, batch);
    bnfc_kernel<<<1, 512>>>(gamma, beta, fcW, fcb, out);
}